// round 5
// baseline (speedup 1.0000x reference)
#include <cuda_runtime.h>
#include <cuda_fp16.h>
#include <cstdint>

// ---------------------------------------------------------------------------
// Problem constants
// ---------------------------------------------------------------------------
#define ROWS_TOTAL 50176        // 256*14*14
#define KDIM       384
#define NDIM       1536
#define M_TILE     128
#define N_TILE     128
#define K_CHUNK    32
#define NUM_KC     (KDIM / K_CHUNK)   // 12
#define STAGES     4                  // NUM_KC % STAGES == 0 (continuous pipeline)
#define LN_EPS     1e-6f

#define N_TILES_N  (NDIM / N_TILE)            // 12
#define N_TILES_M  (ROWS_TOTAL / M_TILE)      // 392
#define NTILES     (N_TILES_N * N_TILES_M)    // 4704
#define GRID_GEMM  296                        // 2 CTAs x 148 SMs, persistent

// fp16 scratch (no cudaMalloc allowed -> __device__ globals)
__device__ __half g_xh[(size_t)ROWS_TOTAL * KDIM];   // LN-applied X, fp16
__device__ __half g_wh[(size_t)NDIM * KDIM];         // W, fp16

// ---------------------------------------------------------------------------
// Inline PTX (baseline features only: ldmatrix / mma.sync / cp.async)
// ---------------------------------------------------------------------------
__device__ __forceinline__ uint32_t smem_u32(const void* p) {
    uint32_t a;
    asm("{ .reg .u64 t; cvta.to.shared.u64 t, %1; cvt.u32.u64 %0, t; }"
        : "=r"(a) : "l"(p));
    return a;
}

#define CP_ASYNC16(saddr, gptr) \
    asm volatile("cp.async.cg.shared.global [%0], [%1], 16;" \
                 :: "r"(saddr), "l"(gptr))

#define CP_COMMIT() asm volatile("cp.async.commit_group;")
#define CP_WAIT(n)  asm volatile("cp.async.wait_group %0;" :: "n"(n))

#define LDSM_X4(r, addr) \
    asm volatile("ldmatrix.sync.aligned.m8n8.x4.shared.b16 {%0,%1,%2,%3}, [%4];" \
                 : "=r"((r)[0]), "=r"((r)[1]), "=r"((r)[2]), "=r"((r)[3]) \
                 : "r"(addr))

#define MMA16816(c, a, b0v, b1v) \
    asm volatile("mma.sync.aligned.m16n8k16.row.col.f32.f16.f16.f32 " \
                 "{%0,%1,%2,%3}, {%4,%5,%6,%7}, {%8,%9}, {%0,%1,%2,%3};" \
                 : "+f"((c)[0]), "+f"((c)[1]), "+f"((c)[2]), "+f"((c)[3]) \
                 : "r"((a)[0]), "r"((a)[1]), "r"((a)[2]), "r"((a)[3]), \
                   "r"(b0v), "r"(b1v))

// ---------------------------------------------------------------------------
// SMEM: per stage { A [128][40] | B [128][40] }, 80B padded rows (conflict-free)
// ---------------------------------------------------------------------------
#define ROW_B      80
#define TILE_B     (M_TILE * ROW_B)       // 10240
#define OFF_A      0
#define OFF_B      TILE_B
#define STAGE_B    (2 * TILE_B)           // 20480
#define SMEM_TOTAL (STAGES * STAGE_B)     // 81920 -> 2 CTAs/SM

__device__ __forceinline__ float gelu_exact(float v) {
    return 0.5f * v * (1.0f + erff(v * 0.70710678118654752f));
}

// ---------------------------------------------------------------------------
// Kernel 1: fused prepass. Blocks [0, 6272): LayerNorm -> fp16 X.
//           Blocks [6272, 6848): W fp32 -> fp16 convert.
// ---------------------------------------------------------------------------
#define LN_BLOCKS  (ROWS_TOTAL / 8)            // 6272
#define WC_BLOCKS  ((NDIM * KDIM) / 1024)      // 576

__global__ __launch_bounds__(256) void prepass_kernel(
    const float* __restrict__ x,
    const float* __restrict__ gamma,
    const float* __restrict__ beta,
    const float* __restrict__ W)
{
    if (blockIdx.x >= LN_BLOCKS) {
        int idx = ((blockIdx.x - LN_BLOCKS) * 256 + threadIdx.x) * 4;
        float4 wv = *reinterpret_cast<const float4*>(W + idx);
        __half2* p = reinterpret_cast<__half2*>(g_wh + idx);
        p[0] = __half2(__float2half_rn(wv.x), __float2half_rn(wv.y));
        p[1] = __half2(__float2half_rn(wv.z), __float2half_rn(wv.w));
        return;
    }

    int row  = blockIdx.x * 8 + (threadIdx.x >> 5);
    int lane = threadIdx.x & 31;
    const float4* xr = reinterpret_cast<const float4*>(x + (size_t)row * KDIM);

    float4 v[3];
    float s = 0.f, ss = 0.f;
#pragma unroll
    for (int i = 0; i < 3; i++) {
        v[i] = xr[lane + i * 32];
        s  += v[i].x + v[i].y + v[i].z + v[i].w;
        ss += v[i].x * v[i].x + v[i].y * v[i].y + v[i].z * v[i].z + v[i].w * v[i].w;
    }
#pragma unroll
    for (int o = 16; o > 0; o >>= 1) {
        s  += __shfl_xor_sync(0xffffffffu, s, o);
        ss += __shfl_xor_sync(0xffffffffu, ss, o);
    }
    float mu  = s * (1.0f / KDIM);
    float var = ss * (1.0f / KDIM) - mu * mu;
    float rs  = rsqrtf(var + LN_EPS);

#pragma unroll
    for (int i = 0; i < 3; i++) {
        int col = (lane + i * 32) * 4;
        float4 gv = *reinterpret_cast<const float4*>(gamma + col);
        float4 bv = *reinterpret_cast<const float4*>(beta + col);
        float n0 = fmaf(v[i].x - mu, rs * gv.x, bv.x);
        float n1 = fmaf(v[i].y - mu, rs * gv.y, bv.y);
        float n2 = fmaf(v[i].z - mu, rs * gv.z, bv.z);
        float n3 = fmaf(v[i].w - mu, rs * gv.w, bv.w);

        __half2* p = reinterpret_cast<__half2*>(g_xh + (size_t)row * KDIM + col);
        p[0] = __half2(__float2half_rn(n0), __float2half_rn(n1));
        p[1] = __half2(__float2half_rn(n2), __float2half_rn(n3));
    }
}

// ---------------------------------------------------------------------------
// Kernel 2: persistent fp16 GEMM + bias + exact GELU
// 256 threads = 8 warps; warp grid 2(M) x 4(N); warp tile 64x32
// Continuous cross-tile cp.async pipeline (stages never drain).
// ---------------------------------------------------------------------------
__device__ __forceinline__ void load_chunk(
    uint32_t sbase, int tile, int chunk, int tid)
{
    const int m0 = (tile / N_TILES_N) * M_TILE;
    const int n0 = (tile % N_TILES_N) * N_TILE;
    const int k0 = chunk * K_CHUNK;
#pragma unroll
    for (int i = 0; i < 2; i++) {
        int idx = tid + i * 256;        // 512 x 16B chunks per tile
        int r = idx >> 2;
        int c = idx & 3;
        size_t ga = (size_t)(m0 + r) * KDIM + k0 + c * 8;
        size_t gb = (size_t)(n0 + r) * KDIM + k0 + c * 8;
        uint32_t so = (uint32_t)(r * ROW_B + c * 16);
        CP_ASYNC16(sbase + OFF_A + so, g_xh + ga);
        CP_ASYNC16(sbase + OFF_B + so, g_wh + gb);
    }
}

__global__ __launch_bounds__(256, 2) void gemm_kernel(
    const float* __restrict__ bias,
    float* __restrict__ out)
{
    extern __shared__ char smem[];
    const uint32_t smem_base = smem_u32(smem);

    const int tid    = threadIdx.x;
    const int wid    = tid >> 5;
    const int lane   = tid & 31;
    const int warp_m = wid & 1;
    const int warp_n = wid >> 1;
    const int lrow   = lane & 15;
    const int lsel   = lane >> 4;
    const int tg     = lane & 3;
    const int gp     = lane >> 2;

    int t = blockIdx.x;                  // first tile for this persistent CTA

    // prologue: prefetch STAGES-1 chunks of the first tile
#pragma unroll
    for (int c = 0; c < STAGES - 1; c++) {
        load_chunk(smem_base + c * STAGE_B, t, c, tid);
        CP_COMMIT();
    }

    while (t < NTILES) {
        const int tn = t + GRID_GEMM;
        const bool has_next = (tn < NTILES);

        float acc[4][4][4];
#pragma unroll
        for (int a = 0; a < 4; a++)
#pragma unroll
            for (int b = 0; b < 4; b++)
#pragma unroll
                for (int c = 0; c < 4; c++) acc[a][b][c] = 0.f;

        for (int kc = 0; kc < NUM_KC; kc++) {
            CP_WAIT(STAGES - 2);
            __syncthreads();

            // prefetch: this tile's chunk kc+3, or the NEXT tile's chunk
            // (stage index stays (kc+3)%STAGES since NUM_KC%STAGES==0)
            const int f = kc + (STAGES - 1);
            if (f < NUM_KC)
                load_chunk(smem_base + (f % STAGES) * STAGE_B, t, f, tid);
            else if (has_next)
                load_chunk(smem_base + (f % STAGES) * STAGE_B, tn, f - NUM_KC, tid);
            CP_COMMIT();

            const uint32_t st = smem_base + (kc % STAGES) * STAGE_B;

#pragma unroll
            for (int ks = 0; ks < 2; ks++) {
                uint32_t af[4][4], bf[2][4];
#pragma unroll
                for (int mf = 0; mf < 4; mf++) {
                    uint32_t ad = st + OFF_A +
                        (uint32_t)((warp_m * 64 + mf * 16 + lrow) * ROW_B + ks * 32 + lsel * 16);
                    LDSM_X4(af[mf], ad);
                }
#pragma unroll
                for (int nf2 = 0; nf2 < 2; nf2++) {
                    uint32_t bd = st + OFF_B +
                        (uint32_t)((warp_n * 32 + nf2 * 16 + lrow) * ROW_B + ks * 32 + lsel * 16);
                    LDSM_X4(bf[nf2], bd);
                }
#pragma unroll
                for (int mf = 0; mf < 4; mf++) {
#pragma unroll
                    for (int nf = 0; nf < 4; nf++) {
                        const int n2 = nf >> 1, sel = nf & 1;
                        MMA16816(acc[mf][nf], af[mf], bf[n2][sel], bf[n2][sel + 2]);
                    }
                }
            }
        }

        // epilogue (no smem use; overlaps next tile's in-flight cp.async)
        {
            const int m0 = (t / N_TILES_N) * M_TILE;
            const int n0 = (t % N_TILES_N) * N_TILE;
#pragma unroll
            for (int mf = 0; mf < 4; mf++) {
#pragma unroll
                for (int nf = 0; nf < 4; nf++) {
                    int row = m0 + warp_m * 64 + mf * 16 + gp;
                    int col = n0 + warp_n * 32 + nf * 8 + tg * 2;
                    float2 bv = *reinterpret_cast<const float2*>(bias + col);
                    float2 o0, o1;
                    o0.x = gelu_exact(acc[mf][nf][0] + bv.x);
                    o0.y = gelu_exact(acc[mf][nf][1] + bv.y);
                    o1.x = gelu_exact(acc[mf][nf][2] + bv.x);
                    o1.y = gelu_exact(acc[mf][nf][3] + bv.y);
                    *reinterpret_cast<float2*>(out + (size_t)row * NDIM + col) = o0;
                    *reinterpret_cast<float2*>(out + (size_t)(row + 8) * NDIM + col) = o1;
                }
            }
        }

        t = tn;
    }
}

// ---------------------------------------------------------------------------
// Launch
// ---------------------------------------------------------------------------
extern "C" void kernel_launch(void* const* d_in, const int* in_sizes, int n_in,
                              void* d_out, int out_size) {
    const float* x     = (const float*)d_in[0];
    const float* gamma = (const float*)d_in[1];
    const float* beta  = (const float*)d_in[2];
    const float* W     = (const float*)d_in[3];
    const float* b     = (const float*)d_in[4];
    float* out = (float*)d_out;

    prepass_kernel<<<LN_BLOCKS + WC_BLOCKS, 256>>>(x, gamma, beta, W);

    cudaFuncSetAttribute(gemm_kernel,
                         cudaFuncAttributeMaxDynamicSharedMemorySize, SMEM_TOTAL);
    gemm_kernel<<<GRID_GEMM, 256, SMEM_TOTAL>>>(b, out);
}

// round 6
// speedup vs baseline: 1.0870x; 1.0870x over previous
#include <cuda_runtime.h>
#include <cuda_fp16.h>
#include <cstdint>

// ---------------------------------------------------------------------------
// Problem constants
// ---------------------------------------------------------------------------
#define ROWS_TOTAL 50176        // 256*14*14
#define KDIM       384
#define NDIM       1536
#define M_TILE     128
#define N_TILE     128
#define K_CHUNK    32
#define NUM_KC     (KDIM / K_CHUNK)   // 12
#define STAGES     5
#define LN_EPS     1e-6f

// fp16 scratch (no cudaMalloc allowed -> __device__ globals)
__device__ __half g_xh[(size_t)ROWS_TOTAL * KDIM];   // LN-applied X, fp16
__device__ __half g_wh[(size_t)NDIM * KDIM];         // W, fp16

// ---------------------------------------------------------------------------
// Inline PTX (baseline features only: ldmatrix / mma.sync / cp.async)
// ---------------------------------------------------------------------------
__device__ __forceinline__ uint32_t smem_u32(const void* p) {
    uint32_t a;
    asm("{ .reg .u64 t; cvta.to.shared.u64 t, %1; cvt.u32.u64 %0, t; }"
        : "=r"(a) : "l"(p));
    return a;
}

#define CP_ASYNC16(saddr, gptr) \
    asm volatile("cp.async.cg.shared.global [%0], [%1], 16;" \
                 :: "r"(saddr), "l"(gptr))

#define CP_COMMIT() asm volatile("cp.async.commit_group;")
#define CP_WAIT(n)  asm volatile("cp.async.wait_group %0;" :: "n"(n))

#define LDSM_X4(r, addr) \
    asm volatile("ldmatrix.sync.aligned.m8n8.x4.shared.b16 {%0,%1,%2,%3}, [%4];" \
                 : "=r"((r)[0]), "=r"((r)[1]), "=r"((r)[2]), "=r"((r)[3]) \
                 : "r"(addr))

#define MMA16816(c, a, b0v, b1v) \
    asm volatile("mma.sync.aligned.m16n8k16.row.col.f32.f16.f16.f32 " \
                 "{%0,%1,%2,%3}, {%4,%5,%6,%7}, {%8,%9}, {%0,%1,%2,%3};" \
                 : "+f"((c)[0]), "+f"((c)[1]), "+f"((c)[2]), "+f"((c)[3]) \
                 : "r"((a)[0]), "r"((a)[1]), "r"((a)[2]), "r"((a)[3]), \
                   "r"(b0v), "r"(b1v))

// ---------------------------------------------------------------------------
// SMEM: per stage { A [128][40] | B [128][40] }, 80B padded rows (conflict-free)
// ---------------------------------------------------------------------------
#define ROW_B      80
#define TILE_B     (M_TILE * ROW_B)       // 10240
#define OFF_A      0
#define OFF_B      TILE_B
#define STAGE_B    (2 * TILE_B)           // 20480
#define SMEM_TOTAL (STAGES * STAGE_B)     // 102400 -> 2 CTAs/SM (200KB)

__device__ __forceinline__ float gelu_exact(float v) {
    return 0.5f * v * (1.0f + erff(v * 0.70710678118654752f));
}

// ---------------------------------------------------------------------------
// Kernel 1: fused prepass. Blocks [0, 6272): LayerNorm -> fp16 X.
//           Blocks [6272, 6848): W fp32 -> fp16 convert.
// ---------------------------------------------------------------------------
#define LN_BLOCKS  (ROWS_TOTAL / 8)            // 6272
#define WC_BLOCKS  ((NDIM * KDIM) / 1024)      // 576

__global__ __launch_bounds__(256) void prepass_kernel(
    const float* __restrict__ x,
    const float* __restrict__ gamma,
    const float* __restrict__ beta,
    const float* __restrict__ W)
{
    if (blockIdx.x >= LN_BLOCKS) {
        int idx = ((blockIdx.x - LN_BLOCKS) * 256 + threadIdx.x) * 4;
        float4 wv = *reinterpret_cast<const float4*>(W + idx);
        __half2* p = reinterpret_cast<__half2*>(g_wh + idx);
        p[0] = __half2(__float2half_rn(wv.x), __float2half_rn(wv.y));
        p[1] = __half2(__float2half_rn(wv.z), __float2half_rn(wv.w));
        return;
    }

    int row  = blockIdx.x * 8 + (threadIdx.x >> 5);
    int lane = threadIdx.x & 31;
    const float4* xr = reinterpret_cast<const float4*>(x + (size_t)row * KDIM);

    float4 v[3];
    float s = 0.f, ss = 0.f;
#pragma unroll
    for (int i = 0; i < 3; i++) {
        v[i] = xr[lane + i * 32];
        s  += v[i].x + v[i].y + v[i].z + v[i].w;
        ss += v[i].x * v[i].x + v[i].y * v[i].y + v[i].z * v[i].z + v[i].w * v[i].w;
    }
#pragma unroll
    for (int o = 16; o > 0; o >>= 1) {
        s  += __shfl_xor_sync(0xffffffffu, s, o);
        ss += __shfl_xor_sync(0xffffffffu, ss, o);
    }
    float mu  = s * (1.0f / KDIM);
    float var = ss * (1.0f / KDIM) - mu * mu;
    float rs  = rsqrtf(var + LN_EPS);

#pragma unroll
    for (int i = 0; i < 3; i++) {
        int col = (lane + i * 32) * 4;
        float4 gv = *reinterpret_cast<const float4*>(gamma + col);
        float4 bv = *reinterpret_cast<const float4*>(beta + col);
        float n0 = fmaf(v[i].x - mu, rs * gv.x, bv.x);
        float n1 = fmaf(v[i].y - mu, rs * gv.y, bv.y);
        float n2 = fmaf(v[i].z - mu, rs * gv.z, bv.z);
        float n3 = fmaf(v[i].w - mu, rs * gv.w, bv.w);

        __half2* p = reinterpret_cast<__half2*>(g_xh + (size_t)row * KDIM + col);
        p[0] = __half2(__float2half_rn(n0), __float2half_rn(n1));
        p[1] = __half2(__float2half_rn(n2), __float2half_rn(n3));
    }
}

// ---------------------------------------------------------------------------
// Kernel 2: fp16 GEMM + bias + exact GELU (non-persistent, 5-stage pipeline)
// 256 threads = 8 warps; warp grid 2(M) x 4(N); warp tile 64x32
// ---------------------------------------------------------------------------
__device__ __forceinline__ void load_stage(
    uint32_t sbase, int m0, int n0, int k0, int tid)
{
#pragma unroll
    for (int i = 0; i < 2; i++) {
        int idx = tid + i * 256;        // 512 x 16B chunks per tile
        int r = idx >> 2;
        int c = idx & 3;
        size_t ga = (size_t)(m0 + r) * KDIM + k0 + c * 8;
        size_t gb = (size_t)(n0 + r) * KDIM + k0 + c * 8;
        uint32_t so = (uint32_t)(r * ROW_B + c * 16);
        CP_ASYNC16(sbase + OFF_A + so, g_xh + ga);
        CP_ASYNC16(sbase + OFF_B + so, g_wh + gb);
    }
}

__global__ __launch_bounds__(256, 2) void gemm_kernel(
    const float* __restrict__ bias,
    float* __restrict__ out)
{
    extern __shared__ char smem[];
    const uint32_t smem_base = smem_u32(smem);

    const int tid    = threadIdx.x;
    const int wid    = tid >> 5;
    const int lane   = tid & 31;
    const int warp_m = wid & 1;
    const int warp_n = wid >> 1;
    const int lrow   = lane & 15;
    const int lsel   = lane >> 4;

    const int n0 = blockIdx.x * N_TILE;   // n fastest -> X-tile L2 reuse
    const int m0 = blockIdx.y * M_TILE;

    // Hoisted ldmatrix base offsets (per-thread invariants)
    uint32_t a_base[4], b_base[2];
#pragma unroll
    for (int mf = 0; mf < 4; mf++)
        a_base[mf] = (uint32_t)(OFF_A + (warp_m * 64 + mf * 16 + lrow) * ROW_B + lsel * 16);
#pragma unroll
    for (int nf2 = 0; nf2 < 2; nf2++)
        b_base[nf2] = (uint32_t)(OFF_B + (warp_n * 32 + nf2 * 16 + lrow) * ROW_B + lsel * 16);

    // prologue: prefetch STAGES-1 stages
#pragma unroll
    for (int s = 0; s < STAGES - 1; s++) {
        load_stage(smem_base + s * STAGE_B, m0, n0, s * K_CHUNK, tid);
        CP_COMMIT();
    }

    float acc[4][4][4];
#pragma unroll
    for (int a = 0; a < 4; a++)
#pragma unroll
        for (int b = 0; b < 4; b++)
#pragma unroll
            for (int c = 0; c < 4; c++) acc[a][b][c] = 0.f;

    int sread = 0, swrite = STAGES - 1;

    for (int kc = 0; kc < NUM_KC; kc++) {
        CP_WAIT(STAGES - 2);
        __syncthreads();

        if (kc + STAGES - 1 < NUM_KC)
            load_stage(smem_base + swrite * STAGE_B, m0, n0,
                       (kc + STAGES - 1) * K_CHUNK, tid);
        CP_COMMIT();
        if (++swrite == STAGES) swrite = 0;

        const uint32_t st = smem_base + sread * STAGE_B;
        if (++sread == STAGES) sread = 0;

#pragma unroll
        for (int ks = 0; ks < 2; ks++) {
            uint32_t af[4][4], bf[2][4];
#pragma unroll
            for (int nf2 = 0; nf2 < 2; nf2++)
                LDSM_X4(bf[nf2], st + b_base[nf2] + ks * 32);
#pragma unroll
            for (int mf = 0; mf < 4; mf++)
                LDSM_X4(af[mf], st + a_base[mf] + ks * 32);
#pragma unroll
            for (int mf = 0; mf < 4; mf++) {
#pragma unroll
                for (int nf = 0; nf < 4; nf++) {
                    const int n2 = nf >> 1, sel = nf & 1;
                    MMA16816(acc[mf][nf], af[mf], bf[n2][sel], bf[n2][sel + 2]);
                }
            }
        }
    }

    // epilogue: bias + exact GELU, direct float2 stores (sectors fully covered)
    const int tg = lane & 3, gp = lane >> 2;
#pragma unroll
    for (int mf = 0; mf < 4; mf++) {
#pragma unroll
        for (int nf = 0; nf < 4; nf++) {
            int row = m0 + warp_m * 64 + mf * 16 + gp;
            int col = n0 + warp_n * 32 + nf * 8 + tg * 2;
            float2 bv = *reinterpret_cast<const float2*>(bias + col);
            float2 o0, o1;
            o0.x = gelu_exact(acc[mf][nf][0] + bv.x);
            o0.y = gelu_exact(acc[mf][nf][1] + bv.y);
            o1.x = gelu_exact(acc[mf][nf][2] + bv.x);
            o1.y = gelu_exact(acc[mf][nf][3] + bv.y);
            *reinterpret_cast<float2*>(out + (size_t)row * NDIM + col) = o0;
            *reinterpret_cast<float2*>(out + (size_t)(row + 8) * NDIM + col) = o1;
        }
    }
}

// ---------------------------------------------------------------------------
// Launch
// ---------------------------------------------------------------------------
extern "C" void kernel_launch(void* const* d_in, const int* in_sizes, int n_in,
                              void* d_out, int out_size) {
    const float* x     = (const float*)d_in[0];
    const float* gamma = (const float*)d_in[1];
    const float* beta  = (const float*)d_in[2];
    const float* W     = (const float*)d_in[3];
    const float* b     = (const float*)d_in[4];
    float* out = (float*)d_out;

    prepass_kernel<<<LN_BLOCKS + WC_BLOCKS, 256>>>(x, gamma, beta, W);

    cudaFuncSetAttribute(gemm_kernel,
                         cudaFuncAttributeMaxDynamicSharedMemorySize, SMEM_TOTAL);
    dim3 grid(NDIM / N_TILE, ROWS_TOTAL / M_TILE);   // (12, 392)
    gemm_kernel<<<grid, 256, SMEM_TOTAL>>>(b, out);
}

// round 7
// speedup vs baseline: 1.1156x; 1.0263x over previous
#include <cuda_runtime.h>
#include <cuda_fp16.h>
#include <cstdint>

// ---------------------------------------------------------------------------
// Problem constants
// ---------------------------------------------------------------------------
#define ROWS_TOTAL 50176        // 256*14*14
#define KDIM       384
#define NDIM       1536
#define M_TILE     128
#define N_TILE     64
#define K_CHUNK    32
#define NUM_KC     (KDIM / K_CHUNK)   // 12
#define STAGES     4
#define LN_EPS     1e-6f

// fp16 scratch (no cudaMalloc allowed -> __device__ globals)
__device__ __half g_xh[(size_t)ROWS_TOTAL * KDIM];   // LN-applied X, fp16
__device__ __half g_wh[(size_t)NDIM * KDIM];         // W, fp16

// ---------------------------------------------------------------------------
// Inline PTX (baseline features only: ldmatrix / mma.sync / cp.async)
// ---------------------------------------------------------------------------
__device__ __forceinline__ uint32_t smem_u32(const void* p) {
    uint32_t a;
    asm("{ .reg .u64 t; cvta.to.shared.u64 t, %1; cvt.u32.u64 %0, t; }"
        : "=r"(a) : "l"(p));
    return a;
}

#define CP_ASYNC16(saddr, gptr) \
    asm volatile("cp.async.cg.shared.global [%0], [%1], 16;" \
                 :: "r"(saddr), "l"(gptr))

#define CP_COMMIT() asm volatile("cp.async.commit_group;")
#define CP_WAIT(n)  asm volatile("cp.async.wait_group %0;" :: "n"(n))

#define LDSM_X4(r, addr) \
    asm volatile("ldmatrix.sync.aligned.m8n8.x4.shared.b16 {%0,%1,%2,%3}, [%4];" \
                 : "=r"((r)[0]), "=r"((r)[1]), "=r"((r)[2]), "=r"((r)[3]) \
                 : "r"(addr))

#define MMA16816(c, a, b0v, b1v) \
    asm volatile("mma.sync.aligned.m16n8k16.row.col.f32.f16.f16.f32 " \
                 "{%0,%1,%2,%3}, {%4,%5,%6,%7}, {%8,%9}, {%0,%1,%2,%3};" \
                 : "+f"((c)[0]), "+f"((c)[1]), "+f"((c)[2]), "+f"((c)[3]) \
                 : "r"((a)[0]), "r"((a)[1]), "r"((a)[2]), "r"((a)[3]), \
                   "r"(b0v), "r"(b1v))

// ---------------------------------------------------------------------------
// SMEM: per stage { A [128][40] | B [64][40] }, 80B padded rows (conflict-free)
// ---------------------------------------------------------------------------
#define ROW_B      80
#define OFF_A      0
#define OFF_B      (M_TILE * ROW_B)               // 10240
#define STAGE_B    ((M_TILE + N_TILE) * ROW_B)    // 15360
#define SMEM_TOTAL (STAGES * STAGE_B)             // 61440 -> 3 CTAs/SM (184KB)

__device__ __forceinline__ float gelu_exact(float v) {
    return 0.5f * v * (1.0f + erff(v * 0.70710678118654752f));
}

// ---------------------------------------------------------------------------
// Kernel 1: fused prepass. Blocks [0, 6272): LayerNorm -> fp16 X.
//           Blocks [6272, 6848): W fp32 -> fp16 convert.
// ---------------------------------------------------------------------------
#define LN_BLOCKS  (ROWS_TOTAL / 8)            // 6272
#define WC_BLOCKS  ((NDIM * KDIM) / 1024)      // 576

__global__ __launch_bounds__(256) void prepass_kernel(
    const float* __restrict__ x,
    const float* __restrict__ gamma,
    const float* __restrict__ beta,
    const float* __restrict__ W)
{
    if (blockIdx.x >= LN_BLOCKS) {
        int idx = ((blockIdx.x - LN_BLOCKS) * 256 + threadIdx.x) * 4;
        float4 wv = *reinterpret_cast<const float4*>(W + idx);
        __half2* p = reinterpret_cast<__half2*>(g_wh + idx);
        p[0] = __half2(__float2half_rn(wv.x), __float2half_rn(wv.y));
        p[1] = __half2(__float2half_rn(wv.z), __float2half_rn(wv.w));
        return;
    }

    int row  = blockIdx.x * 8 + (threadIdx.x >> 5);
    int lane = threadIdx.x & 31;
    const float4* xr = reinterpret_cast<const float4*>(x + (size_t)row * KDIM);

    float4 v[3];
    float s = 0.f, ss = 0.f;
#pragma unroll
    for (int i = 0; i < 3; i++) {
        v[i] = xr[lane + i * 32];
        s  += v[i].x + v[i].y + v[i].z + v[i].w;
        ss += v[i].x * v[i].x + v[i].y * v[i].y + v[i].z * v[i].z + v[i].w * v[i].w;
    }
#pragma unroll
    for (int o = 16; o > 0; o >>= 1) {
        s  += __shfl_xor_sync(0xffffffffu, s, o);
        ss += __shfl_xor_sync(0xffffffffu, ss, o);
    }
    float mu  = s * (1.0f / KDIM);
    float var = ss * (1.0f / KDIM) - mu * mu;
    float rs  = rsqrtf(var + LN_EPS);

#pragma unroll
    for (int i = 0; i < 3; i++) {
        int col = (lane + i * 32) * 4;
        float4 gv = *reinterpret_cast<const float4*>(gamma + col);
        float4 bv = *reinterpret_cast<const float4*>(beta + col);
        float n0 = fmaf(v[i].x - mu, rs * gv.x, bv.x);
        float n1 = fmaf(v[i].y - mu, rs * gv.y, bv.y);
        float n2 = fmaf(v[i].z - mu, rs * gv.z, bv.z);
        float n3 = fmaf(v[i].w - mu, rs * gv.w, bv.w);

        __half2* p = reinterpret_cast<__half2*>(g_xh + (size_t)row * KDIM + col);
        p[0] = __half2(__float2half_rn(n0), __float2half_rn(n1));
        p[1] = __half2(__float2half_rn(n2), __float2half_rn(n3));
    }
}

// ---------------------------------------------------------------------------
// Kernel 2: fp16 GEMM + bias + exact GELU
// CTA tile 128x64; 256 threads = 8 warps; warp grid 4(M) x 2(N); warp 32x32
// 4-stage cp.async pipeline, 3 CTAs/SM
// ---------------------------------------------------------------------------
__global__ __launch_bounds__(256, 3) void gemm_kernel(
    const float* __restrict__ bias,
    float* __restrict__ out)
{
    extern __shared__ char smem[];
    const uint32_t smem_base = smem_u32(smem);

    const int tid    = threadIdx.x;
    const int wid    = tid >> 5;
    const int lane   = tid & 31;
    const int warp_m = wid & 3;          // 0..3 (32-row quarters)
    const int warp_n = wid >> 2;         // 0..1 (32-col halves)
    const int lrow   = lane & 15;
    const int lsel   = lane >> 4;

    const int n0 = blockIdx.x * N_TILE;  // n fastest -> X-tile L2 reuse
    const int m0 = blockIdx.y * M_TILE;

    // --- per-thread load pointers (3 x 16B cp.async per stage) ---
    const int ldr = tid >> 2;            // 0..63
    const int ldc = tid & 3;             // 16B chunk in row
    const __half* pa = g_xh + (size_t)(m0 + ldr) * KDIM + ldc * 8;   // A rows 0..63
    const __half* pb = g_wh + (size_t)(n0 + ldr) * KDIM + ldc * 8;   // B rows 0..63
    const uint32_t so = (uint32_t)(ldr * ROW_B + ldc * 16);
    // A rows 64..127 use pa + 64*KDIM, smem offset so + 64*ROW_B

#define LOAD_STAGE(sb, k0)                                          \
    do {                                                            \
        CP_ASYNC16((sb) + OFF_A + so,            pa + (k0));        \
        CP_ASYNC16((sb) + OFF_A + so + 64*ROW_B, pa + 64*KDIM + (k0)); \
        CP_ASYNC16((sb) + OFF_B + so,            pb + (k0));        \
    } while (0)

    // --- hoisted ldmatrix base offsets ---
    uint32_t a_base[2], b_base[2];
#pragma unroll
    for (int mf = 0; mf < 2; mf++)
        a_base[mf] = (uint32_t)(OFF_A + (warp_m * 32 + mf * 16 + lrow) * ROW_B + lsel * 16);
#pragma unroll
    for (int nf2 = 0; nf2 < 2; nf2++)
        b_base[nf2] = (uint32_t)(OFF_B + (warp_n * 32 + nf2 * 16 + lrow) * ROW_B + lsel * 16);

    // prologue: prefetch STAGES-1 stages
#pragma unroll
    for (int s = 0; s < STAGES - 1; s++) {
        LOAD_STAGE(smem_base + s * STAGE_B, s * K_CHUNK);
        CP_COMMIT();
    }

    float acc[2][4][4];
#pragma unroll
    for (int a = 0; a < 2; a++)
#pragma unroll
        for (int b = 0; b < 4; b++)
#pragma unroll
            for (int c = 0; c < 4; c++) acc[a][b][c] = 0.f;

    int sread = 0, swrite = STAGES - 1;

    for (int kc = 0; kc < NUM_KC; kc++) {
        CP_WAIT(STAGES - 2);
        __syncthreads();

        if (kc + STAGES - 1 < NUM_KC)
            LOAD_STAGE(smem_base + swrite * STAGE_B, (kc + STAGES - 1) * K_CHUNK);
        CP_COMMIT();
        if (++swrite == STAGES) swrite = 0;

        const uint32_t st = smem_base + sread * STAGE_B;
        if (++sread == STAGES) sread = 0;

#pragma unroll
        for (int ks = 0; ks < 2; ks++) {
            uint32_t af[2][4], bf[2][4];
#pragma unroll
            for (int nf2 = 0; nf2 < 2; nf2++)
                LDSM_X4(bf[nf2], st + b_base[nf2] + ks * 32);
#pragma unroll
            for (int mf = 0; mf < 2; mf++)
                LDSM_X4(af[mf], st + a_base[mf] + ks * 32);
#pragma unroll
            for (int mf = 0; mf < 2; mf++) {
#pragma unroll
                for (int nf = 0; nf < 4; nf++) {
                    const int n2 = nf >> 1, sel = nf & 1;
                    MMA16816(acc[mf][nf], af[mf], bf[n2][sel], bf[n2][sel + 2]);
                }
            }
        }
    }

    // epilogue: bias + exact GELU, direct float2 stores (sectors fully covered)
    const int tg = lane & 3, gp = lane >> 2;
#pragma unroll
    for (int mf = 0; mf < 2; mf++) {
#pragma unroll
        for (int nf = 0; nf < 4; nf++) {
            int row = m0 + warp_m * 32 + mf * 16 + gp;
            int col = n0 + warp_n * 32 + nf * 8 + tg * 2;
            float2 bv = *reinterpret_cast<const float2*>(bias + col);
            float2 o0, o1;
            o0.x = gelu_exact(acc[mf][nf][0] + bv.x);
            o0.y = gelu_exact(acc[mf][nf][1] + bv.y);
            o1.x = gelu_exact(acc[mf][nf][2] + bv.x);
            o1.y = gelu_exact(acc[mf][nf][3] + bv.y);
            *reinterpret_cast<float2*>(out + (size_t)row * NDIM + col) = o0;
            *reinterpret_cast<float2*>(out + (size_t)(row + 8) * NDIM + col) = o1;
        }
    }
#undef LOAD_STAGE
}

// ---------------------------------------------------------------------------
// Launch
// ---------------------------------------------------------------------------
extern "C" void kernel_launch(void* const* d_in, const int* in_sizes, int n_in,
                              void* d_out, int out_size) {
    const float* x     = (const float*)d_in[0];
    const float* gamma = (const float*)d_in[1];
    const float* beta  = (const float*)d_in[2];
    const float* W     = (const float*)d_in[3];
    const float* b     = (const float*)d_in[4];
    float* out = (float*)d_out;

    prepass_kernel<<<LN_BLOCKS + WC_BLOCKS, 256>>>(x, gamma, beta, W);

    cudaFuncSetAttribute(gemm_kernel,
                         cudaFuncAttributeMaxDynamicSharedMemorySize, SMEM_TOTAL);
    dim3 grid(NDIM / N_TILE, ROWS_TOTAL / M_TILE);   // (24, 392)
    gemm_kernel<<<grid, 256, SMEM_TOTAL>>>(b, out);
}

// round 8
// speedup vs baseline: 1.1369x; 1.0192x over previous
#include <cuda_runtime.h>
#include <cuda_fp16.h>
#include <cstdint>

// ---------------------------------------------------------------------------
// Problem constants
// ---------------------------------------------------------------------------
#define ROWS_TOTAL 50176        // 256*14*14
#define KDIM       384
#define NDIM       1536
#define M_TILE     128
#define N_TILE     64
#define K_CHUNK    32
#define NUM_KC     (KDIM / K_CHUNK)   // 12
#define STAGES     4
#define LN_EPS     1e-6f

// fp16 scratch (no cudaMalloc allowed -> __device__ globals)
__device__ __half g_xh[(size_t)ROWS_TOTAL * KDIM];   // LN-applied X, fp16
__device__ __half g_wh[(size_t)NDIM * KDIM];         // W, fp16

// ---------------------------------------------------------------------------
// Inline PTX (baseline features only: ldmatrix / mma.sync / cp.async)
// ---------------------------------------------------------------------------
__device__ __forceinline__ uint32_t smem_u32(const void* p) {
    uint32_t a;
    asm("{ .reg .u64 t; cvta.to.shared.u64 t, %1; cvt.u32.u64 %0, t; }"
        : "=r"(a) : "l"(p));
    return a;
}

#define CP_ASYNC16(saddr, gptr) \
    asm volatile("cp.async.cg.shared.global [%0], [%1], 16;" \
                 :: "r"(saddr), "l"(gptr))

#define CP_COMMIT() asm volatile("cp.async.commit_group;")
#define CP_WAIT(n)  asm volatile("cp.async.wait_group %0;" :: "n"(n))

#define LDSM_X4(r, addr) \
    asm volatile("ldmatrix.sync.aligned.m8n8.x4.shared.b16 {%0,%1,%2,%3}, [%4];" \
                 : "=r"((r)[0]), "=r"((r)[1]), "=r"((r)[2]), "=r"((r)[3]) \
                 : "r"(addr))

#define MMA16816(c, a, b0v, b1v) \
    asm volatile("mma.sync.aligned.m16n8k16.row.col.f32.f16.f16.f32 " \
                 "{%0,%1,%2,%3}, {%4,%5,%6,%7}, {%8,%9}, {%0,%1,%2,%3};" \
                 : "+f"((c)[0]), "+f"((c)[1]), "+f"((c)[2]), "+f"((c)[3]) \
                 : "r"((a)[0]), "r"((a)[1]), "r"((a)[2]), "r"((a)[3]), \
                   "r"(b0v), "r"(b1v))

// ---------------------------------------------------------------------------
// SMEM: per stage { A [128][40] | B [64][40] }, 80B padded rows (conflict-free)
// ---------------------------------------------------------------------------
#define ROW_B      80
#define OFF_A      0
#define OFF_B      (M_TILE * ROW_B)               // 10240
#define STAGE_B    ((M_TILE + N_TILE) * ROW_B)    // 15360
#define SMEM_TOTAL (STAGES * STAGE_B)             // 61440 -> 3 CTAs/SM (184KB)

// Fast GELU: v * sigmoid(1.59577(v + 0.044715 v^3)) — branch-free, 2 MUFU.
// Max abs deviation from exact erf-GELU ~5e-4 (|v|~2.5-3), rms ~6e-5.
__device__ __forceinline__ float gelu_fast(float v) {
    float t = v * v;
    float z = 1.5957691216f * v * fmaf(0.044715f, t, 1.0f);
    float e = __expf(-z);
    return __fdividef(v, 1.0f + e);
}

// ---------------------------------------------------------------------------
// Kernel 1: fused prepass. Blocks [0, 6272): LayerNorm -> fp16 X.
//           Blocks [6272, 6848): W fp32 -> fp16 convert.
// ---------------------------------------------------------------------------
#define LN_BLOCKS  (ROWS_TOTAL / 8)            // 6272
#define WC_BLOCKS  ((NDIM * KDIM) / 1024)      // 576

__global__ __launch_bounds__(256) void prepass_kernel(
    const float* __restrict__ x,
    const float* __restrict__ gamma,
    const float* __restrict__ beta,
    const float* __restrict__ W)
{
    if (blockIdx.x >= LN_BLOCKS) {
        int idx = ((blockIdx.x - LN_BLOCKS) * 256 + threadIdx.x) * 4;
        float4 wv = *reinterpret_cast<const float4*>(W + idx);
        __half2* p = reinterpret_cast<__half2*>(g_wh + idx);
        p[0] = __half2(__float2half_rn(wv.x), __float2half_rn(wv.y));
        p[1] = __half2(__float2half_rn(wv.z), __float2half_rn(wv.w));
        return;
    }

    int row  = blockIdx.x * 8 + (threadIdx.x >> 5);
    int lane = threadIdx.x & 31;
    const float4* xr = reinterpret_cast<const float4*>(x + (size_t)row * KDIM);

    float4 v[3];
    float s = 0.f, ss = 0.f;
#pragma unroll
    for (int i = 0; i < 3; i++) {
        v[i] = xr[lane + i * 32];
        s  += v[i].x + v[i].y + v[i].z + v[i].w;
        ss += v[i].x * v[i].x + v[i].y * v[i].y + v[i].z * v[i].z + v[i].w * v[i].w;
    }
#pragma unroll
    for (int o = 16; o > 0; o >>= 1) {
        s  += __shfl_xor_sync(0xffffffffu, s, o);
        ss += __shfl_xor_sync(0xffffffffu, ss, o);
    }
    float mu  = s * (1.0f / KDIM);
    float var = ss * (1.0f / KDIM) - mu * mu;
    float rs  = rsqrtf(var + LN_EPS);

#pragma unroll
    for (int i = 0; i < 3; i++) {
        int col = (lane + i * 32) * 4;
        float4 gv = *reinterpret_cast<const float4*>(gamma + col);
        float4 bv = *reinterpret_cast<const float4*>(beta + col);
        float n0 = fmaf(v[i].x - mu, rs * gv.x, bv.x);
        float n1 = fmaf(v[i].y - mu, rs * gv.y, bv.y);
        float n2 = fmaf(v[i].z - mu, rs * gv.z, bv.z);
        float n3 = fmaf(v[i].w - mu, rs * gv.w, bv.w);

        __half2* p = reinterpret_cast<__half2*>(g_xh + (size_t)row * KDIM + col);
        p[0] = __half2(__float2half_rn(n0), __float2half_rn(n1));
        p[1] = __half2(__float2half_rn(n2), __float2half_rn(n3));
    }
}

// ---------------------------------------------------------------------------
// Kernel 2: fp16 GEMM + bias + fast GELU
// CTA tile 128x64; 256 threads = 8 warps; warp grid 4(M) x 2(N); warp 32x32
// 4-stage cp.async pipeline, fully unrolled kc loop, 3 CTAs/SM
// ---------------------------------------------------------------------------
__global__ __launch_bounds__(256, 3) void gemm_kernel(
    const float* __restrict__ bias,
    float* __restrict__ out)
{
    extern __shared__ char smem[];
    const uint32_t smem_base = smem_u32(smem);

    const int tid    = threadIdx.x;
    const int wid    = tid >> 5;
    const int lane   = tid & 31;
    const int warp_m = wid & 3;          // 0..3 (32-row quarters)
    const int warp_n = wid >> 2;         // 0..1 (32-col halves)
    const int lrow   = lane & 15;
    const int lsel   = lane >> 4;

    const int n0 = blockIdx.x * N_TILE;  // n fastest -> X-tile L2 reuse
    const int m0 = blockIdx.y * M_TILE;

    // --- per-thread load pointers (3 x 16B cp.async per stage) ---
    const int ldr = tid >> 2;            // 0..63
    const int ldc = tid & 3;             // 16B chunk in row
    const __half* pa = g_xh + (size_t)(m0 + ldr) * KDIM + ldc * 8;   // A rows 0..63
    const __half* pb = g_wh + (size_t)(n0 + ldr) * KDIM + ldc * 8;   // B rows 0..63
    const uint32_t so = (uint32_t)(ldr * ROW_B + ldc * 16);

#define LOAD_STAGE(sb, k0)                                          \
    do {                                                            \
        CP_ASYNC16((sb) + OFF_A + so,            pa + (k0));        \
        CP_ASYNC16((sb) + OFF_A + so + 64*ROW_B, pa + 64*KDIM + (k0)); \
        CP_ASYNC16((sb) + OFF_B + so,            pb + (k0));        \
    } while (0)

    // --- hoisted ldmatrix base offsets ---
    uint32_t a_base[2], b_base[2];
#pragma unroll
    for (int mf = 0; mf < 2; mf++)
        a_base[mf] = (uint32_t)(OFF_A + (warp_m * 32 + mf * 16 + lrow) * ROW_B + lsel * 16);
#pragma unroll
    for (int nf2 = 0; nf2 < 2; nf2++)
        b_base[nf2] = (uint32_t)(OFF_B + (warp_n * 32 + nf2 * 16 + lrow) * ROW_B + lsel * 16);

    // prologue: prefetch STAGES-1 stages
#pragma unroll
    for (int s = 0; s < STAGES - 1; s++) {
        LOAD_STAGE(smem_base + s * STAGE_B, s * K_CHUNK);
        CP_COMMIT();
    }

    float acc[2][4][4];
#pragma unroll
    for (int a = 0; a < 2; a++)
#pragma unroll
        for (int b = 0; b < 4; b++)
#pragma unroll
            for (int c = 0; c < 4; c++) acc[a][b][c] = 0.f;

#pragma unroll
    for (int kc = 0; kc < NUM_KC; kc++) {
        CP_WAIT(STAGES - 2);
        __syncthreads();

        if (kc + STAGES - 1 < NUM_KC) {
            LOAD_STAGE(smem_base + ((kc + STAGES - 1) % STAGES) * STAGE_B,
                       (kc + STAGES - 1) * K_CHUNK);
        }
        CP_COMMIT();

        const uint32_t st = smem_base + (kc % STAGES) * STAGE_B;

#pragma unroll
        for (int ks = 0; ks < 2; ks++) {
            uint32_t af[2][4], bf[2][4];
#pragma unroll
            for (int nf2 = 0; nf2 < 2; nf2++)
                LDSM_X4(bf[nf2], st + b_base[nf2] + ks * 32);
#pragma unroll
            for (int mf = 0; mf < 2; mf++)
                LDSM_X4(af[mf], st + a_base[mf] + ks * 32);
#pragma unroll
            for (int mf = 0; mf < 2; mf++) {
#pragma unroll
                for (int nf = 0; nf < 4; nf++) {
                    const int n2 = nf >> 1, sel = nf & 1;
                    MMA16816(acc[mf][nf], af[mf], bf[n2][sel], bf[n2][sel + 2]);
                }
            }
        }
    }

    // epilogue: bias + fast GELU, direct float2 stores (sectors fully covered)
    const int tg = lane & 3, gp = lane >> 2;
#pragma unroll
    for (int mf = 0; mf < 2; mf++) {
#pragma unroll
        for (int nf = 0; nf < 4; nf++) {
            int row = m0 + warp_m * 32 + mf * 16 + gp;
            int col = n0 + warp_n * 32 + nf * 8 + tg * 2;
            float2 bv = *reinterpret_cast<const float2*>(bias + col);
            float2 o0, o1;
            o0.x = gelu_fast(acc[mf][nf][0] + bv.x);
            o0.y = gelu_fast(acc[mf][nf][1] + bv.y);
            o1.x = gelu_fast(acc[mf][nf][2] + bv.x);
            o1.y = gelu_fast(acc[mf][nf][3] + bv.y);
            *reinterpret_cast<float2*>(out + (size_t)row * NDIM + col) = o0;
            *reinterpret_cast<float2*>(out + (size_t)(row + 8) * NDIM + col) = o1;
        }
    }
#undef LOAD_STAGE
}

// ---------------------------------------------------------------------------
// Launch
// ---------------------------------------------------------------------------
extern "C" void kernel_launch(void* const* d_in, const int* in_sizes, int n_in,
                              void* d_out, int out_size) {
    const float* x     = (const float*)d_in[0];
    const float* gamma = (const float*)d_in[1];
    const float* beta  = (const float*)d_in[2];
    const float* W     = (const float*)d_in[3];
    const float* b     = (const float*)d_in[4];
    float* out = (float*)d_out;

    prepass_kernel<<<LN_BLOCKS + WC_BLOCKS, 256>>>(x, gamma, beta, W);

    cudaFuncSetAttribute(gemm_kernel,
                         cudaFuncAttributeMaxDynamicSharedMemorySize, SMEM_TOTAL);
    dim3 grid(NDIM / N_TILE, ROWS_TOTAL / M_TILE);   // (24, 392)
    gemm_kernel<<<grid, 256, SMEM_TOTAL>>>(b, out);
}

// round 9
// speedup vs baseline: 1.1495x; 1.0111x over previous
#include <cuda_runtime.h>
#include <cuda_fp16.h>
#include <cstdint>

// ---------------------------------------------------------------------------
// Problem constants
// ---------------------------------------------------------------------------
#define ROWS_TOTAL 50176        // 256*14*14
#define KDIM       384
#define NDIM       1536
#define M_TILE     128
#define N_TILE     64
#define K_CHUNK    32
#define NUM_KC     (KDIM / K_CHUNK)   // 12
#define STAGES     4
#define LN_EPS     1e-6f

// fp16 scratch (no cudaMalloc allowed -> __device__ globals)
__device__ __half g_xh[(size_t)ROWS_TOTAL * KDIM];   // LN-applied X, fp16
__device__ __half g_wh[(size_t)NDIM * KDIM];         // W, fp16

// ---------------------------------------------------------------------------
// Inline PTX (baseline features only: ldmatrix / mma.sync / cp.async)
// ---------------------------------------------------------------------------
__device__ __forceinline__ uint32_t smem_u32(const void* p) {
    uint32_t a;
    asm("{ .reg .u64 t; cvta.to.shared.u64 t, %1; cvt.u32.u64 %0, t; }"
        : "=r"(a) : "l"(p));
    return a;
}

#define CP_ASYNC16(saddr, gptr) \
    asm volatile("cp.async.cg.shared.global [%0], [%1], 16;" \
                 :: "r"(saddr), "l"(gptr))

#define CP_COMMIT() asm volatile("cp.async.commit_group;")
#define CP_WAIT(n)  asm volatile("cp.async.wait_group %0;" :: "n"(n))

#define LDSM_X4(r, addr) \
    asm volatile("ldmatrix.sync.aligned.m8n8.x4.shared.b16 {%0,%1,%2,%3}, [%4];" \
                 : "=r"((r)[0]), "=r"((r)[1]), "=r"((r)[2]), "=r"((r)[3]) \
                 : "r"(addr))

#define MMA16816(c, a, b0v, b1v) \
    asm volatile("mma.sync.aligned.m16n8k16.row.col.f32.f16.f16.f32 " \
                 "{%0,%1,%2,%3}, {%4,%5,%6,%7}, {%8,%9}, {%0,%1,%2,%3};" \
                 : "+f"((c)[0]), "+f"((c)[1]), "+f"((c)[2]), "+f"((c)[3]) \
                 : "r"((a)[0]), "r"((a)[1]), "r"((a)[2]), "r"((a)[3]), \
                   "r"(b0v), "r"(b1v))

// ---------------------------------------------------------------------------
// SMEM: per stage { A [128][40] | B [64][40] }, 80B padded rows (conflict-free)
// ---------------------------------------------------------------------------
#define ROW_B      80
#define OFF_A      0
#define OFF_B      (M_TILE * ROW_B)               // 10240
#define STAGE_B    ((M_TILE + N_TILE) * ROW_B)    // 15360
#define SMEM_TOTAL (STAGES * STAGE_B)             // 61440 -> 3 CTAs/SM (184KB)

// Fast GELU: v * sigmoid(1.59577(v + 0.044715 v^3)) — branch-free, 2 MUFU.
__device__ __forceinline__ float gelu_fast(float v) {
    float t = v * v;
    float z = 1.5957691216f * v * fmaf(0.044715f, t, 1.0f);
    float e = __expf(-z);
    return __fdividef(v, 1.0f + e);
}

// ---------------------------------------------------------------------------
// Kernel 1: fused prepass. Blocks [0, 6272): LayerNorm -> fp16 X.
//           Blocks [6272, 6848): W fp32 -> fp16 convert.
// ---------------------------------------------------------------------------
#define LN_BLOCKS  (ROWS_TOTAL / 8)            // 6272
#define WC_BLOCKS  ((NDIM * KDIM) / 1024)      // 576

__global__ __launch_bounds__(256) void prepass_kernel(
    const float* __restrict__ x,
    const float* __restrict__ gamma,
    const float* __restrict__ beta,
    const float* __restrict__ W)
{
    if (blockIdx.x >= LN_BLOCKS) {
        int idx = ((blockIdx.x - LN_BLOCKS) * 256 + threadIdx.x) * 4;
        float4 wv = *reinterpret_cast<const float4*>(W + idx);
        __half2* p = reinterpret_cast<__half2*>(g_wh + idx);
        p[0] = __half2(__float2half_rn(wv.x), __float2half_rn(wv.y));
        p[1] = __half2(__float2half_rn(wv.z), __float2half_rn(wv.w));
        return;
    }

    int row  = blockIdx.x * 8 + (threadIdx.x >> 5);
    int lane = threadIdx.x & 31;
    const float4* xr = reinterpret_cast<const float4*>(x + (size_t)row * KDIM);

    float4 v[3];
    float s = 0.f, ss = 0.f;
#pragma unroll
    for (int i = 0; i < 3; i++) {
        v[i] = xr[lane + i * 32];
        s  += v[i].x + v[i].y + v[i].z + v[i].w;
        ss += v[i].x * v[i].x + v[i].y * v[i].y + v[i].z * v[i].z + v[i].w * v[i].w;
    }
#pragma unroll
    for (int o = 16; o > 0; o >>= 1) {
        s  += __shfl_xor_sync(0xffffffffu, s, o);
        ss += __shfl_xor_sync(0xffffffffu, ss, o);
    }
    float mu  = s * (1.0f / KDIM);
    float var = ss * (1.0f / KDIM) - mu * mu;
    float rs  = rsqrtf(var + LN_EPS);

#pragma unroll
    for (int i = 0; i < 3; i++) {
        int col = (lane + i * 32) * 4;
        float4 gv = *reinterpret_cast<const float4*>(gamma + col);
        float4 bv = *reinterpret_cast<const float4*>(beta + col);
        float n0 = fmaf(v[i].x - mu, rs * gv.x, bv.x);
        float n1 = fmaf(v[i].y - mu, rs * gv.y, bv.y);
        float n2 = fmaf(v[i].z - mu, rs * gv.z, bv.z);
        float n3 = fmaf(v[i].w - mu, rs * gv.w, bv.w);

        __half2* p = reinterpret_cast<__half2*>(g_xh + (size_t)row * KDIM + col);
        p[0] = __half2(__float2half_rn(n0), __float2half_rn(n1));
        p[1] = __half2(__float2half_rn(n2), __float2half_rn(n3));
    }
}

// ---------------------------------------------------------------------------
// Kernel 2: fp16 GEMM + bias + fast GELU
// CTA tile 128x64; 8 warps (4M x 2N), warp tile 32x32.
// 4-stage cp.async pipeline + double-buffered register fragments:
// LDSM for step s+1 overlaps MMAs of step s (no smem<->tensor phase alternation).
// ---------------------------------------------------------------------------
__global__ __launch_bounds__(256, 3) void gemm_kernel(
    const float* __restrict__ bias,
    float* __restrict__ out)
{
    extern __shared__ char smem[];
    const uint32_t smem_base = smem_u32(smem);

    const int tid    = threadIdx.x;
    const int wid    = tid >> 5;
    const int lane   = tid & 31;
    const int warp_m = wid & 3;          // 0..3 (32-row quarters)
    const int warp_n = wid >> 2;         // 0..1 (32-col halves)
    const int lrow   = lane & 15;
    const int lsel   = lane >> 4;

    const int n0 = blockIdx.x * N_TILE;  // n fastest -> X-tile L2 reuse
    const int m0 = blockIdx.y * M_TILE;

    // --- per-thread load pointers (3 x 16B cp.async per stage) ---
    const int ldr = tid >> 2;            // 0..63
    const int ldc = tid & 3;             // 16B chunk in row
    const __half* pa = g_xh + (size_t)(m0 + ldr) * KDIM + ldc * 8;
    const __half* pb = g_wh + (size_t)(n0 + ldr) * KDIM + ldc * 8;
    const uint32_t so = (uint32_t)(ldr * ROW_B + ldc * 16);

#define LOAD_STAGE(sb, k0)                                             \
    do {                                                               \
        CP_ASYNC16((sb) + OFF_A + so,            pa + (k0));           \
        CP_ASYNC16((sb) + OFF_A + so + 64*ROW_B, pa + 64*KDIM + (k0)); \
        CP_ASYNC16((sb) + OFF_B + so,            pb + (k0));           \
    } while (0)

    // --- hoisted ldmatrix base offsets ---
    uint32_t a_base[2], b_base[2];
#pragma unroll
    for (int mf = 0; mf < 2; mf++)
        a_base[mf] = (uint32_t)(OFF_A + (warp_m * 32 + mf * 16 + lrow) * ROW_B + lsel * 16);
#pragma unroll
    for (int nf2 = 0; nf2 < 2; nf2++)
        b_base[nf2] = (uint32_t)(OFF_B + (warp_n * 32 + nf2 * 16 + lrow) * ROW_B + lsel * 16);

#define LOAD_FRAGS(buf_a, buf_b, st, ks)                      \
    do {                                                      \
        LDSM_X4((buf_b)[0], (st) + b_base[0] + (ks) * 32);    \
        LDSM_X4((buf_b)[1], (st) + b_base[1] + (ks) * 32);    \
        LDSM_X4((buf_a)[0], (st) + a_base[0] + (ks) * 32);    \
        LDSM_X4((buf_a)[1], (st) + a_base[1] + (ks) * 32);    \
    } while (0)

#define DO_MMAS(buf_a, buf_b)                                                  \
    do {                                                                       \
        _Pragma("unroll")                                                      \
        for (int mf = 0; mf < 2; mf++) {                                       \
            _Pragma("unroll")                                                  \
            for (int nf = 0; nf < 4; nf++) {                                   \
                const int n2 = nf >> 1, sel = nf & 1;                          \
                MMA16816(acc[mf][nf], (buf_a)[mf],                             \
                         (buf_b)[n2][sel], (buf_b)[n2][sel + 2]);              \
            }                                                                  \
        }                                                                      \
    } while (0)

    // prologue: prefetch STAGES-1 stages
#pragma unroll
    for (int s = 0; s < STAGES - 1; s++) {
        LOAD_STAGE(smem_base + s * STAGE_B, s * K_CHUNK);
        CP_COMMIT();
    }

    float acc[2][4][4];
#pragma unroll
    for (int a = 0; a < 2; a++)
#pragma unroll
        for (int b = 0; b < 4; b++)
#pragma unroll
            for (int c = 0; c < 4; c++) acc[a][b][c] = 0.f;

    uint32_t af0[2][4], bf0[2][4], af1[2][4], bf1[2][4];

    // wait for stage 0 and preload its first fragments
    CP_WAIT(STAGES - 2);
    __syncthreads();
    uint32_t st = smem_base;
    LOAD_FRAGS(af0, bf0, st, 0);

#pragma unroll
    for (int kc = 0; kc < NUM_KC; kc++) {
        // issue gmem prefetch for stage kc+3 (empty commit keeps group count aligned)
        if (kc + STAGES - 1 < NUM_KC)
            LOAD_STAGE(smem_base + ((kc + STAGES - 1) % STAGES) * STAGE_B,
                       (kc + STAGES - 1) * K_CHUNK);
        CP_COMMIT();

        // ks = 0: prefetch ks=1 fragments, then MMA on ks=0 fragments
        LOAD_FRAGS(af1, bf1, st, 1);
        DO_MMAS(af0, bf0);

        // ks = 1: advance to next stage (wait+sync), prefetch its ks=0 frags,
        //         then MMA on ks=1 fragments
        if (kc + 1 < NUM_KC) {
            CP_WAIT(STAGES - 2);
            __syncthreads();
            st = smem_base + ((kc + 1) % STAGES) * STAGE_B;
            LOAD_FRAGS(af0, bf0, st, 0);
        }
        DO_MMAS(af1, bf1);
    }

    // epilogue: bias + fast GELU, direct float2 stores (sectors fully covered)
    const int tg = lane & 3, gp = lane >> 2;
#pragma unroll
    for (int mf = 0; mf < 2; mf++) {
#pragma unroll
        for (int nf = 0; nf < 4; nf++) {
            int row = m0 + warp_m * 32 + mf * 16 + gp;
            int col = n0 + warp_n * 32 + nf * 8 + tg * 2;
            float2 bv = *reinterpret_cast<const float2*>(bias + col);
            float2 o0, o1;
            o0.x = gelu_fast(acc[mf][nf][0] + bv.x);
            o0.y = gelu_fast(acc[mf][nf][1] + bv.y);
            o1.x = gelu_fast(acc[mf][nf][2] + bv.x);
            o1.y = gelu_fast(acc[mf][nf][3] + bv.y);
            *reinterpret_cast<float2*>(out + (size_t)row * NDIM + col) = o0;
            *reinterpret_cast<float2*>(out + (size_t)(row + 8) * NDIM + col) = o1;
        }
    }
#undef LOAD_STAGE
#undef LOAD_FRAGS
#undef DO_MMAS
}

// ---------------------------------------------------------------------------
// Launch
// ---------------------------------------------------------------------------
extern "C" void kernel_launch(void* const* d_in, const int* in_sizes, int n_in,
                              void* d_out, int out_size) {
    const float* x     = (const float*)d_in[0];
    const float* gamma = (const float*)d_in[1];
    const float* beta  = (const float*)d_in[2];
    const float* W     = (const float*)d_in[3];
    const float* b     = (const float*)d_in[4];
    float* out = (float*)d_out;

    prepass_kernel<<<LN_BLOCKS + WC_BLOCKS, 256>>>(x, gamma, beta, W);

    cudaFuncSetAttribute(gemm_kernel,
                         cudaFuncAttributeMaxDynamicSharedMemorySize, SMEM_TOTAL);
    dim3 grid(NDIM / N_TILE, ROWS_TOTAL / M_TILE);   // (24, 392)
    gemm_kernel<<<grid, 256, SMEM_TOTAL>>>(b, out);
}

// round 10
// speedup vs baseline: 1.1950x; 1.0395x over previous
#include <cuda_runtime.h>
#include <cuda_fp16.h>
#include <cstdint>

// ---------------------------------------------------------------------------
// Problem constants
// ---------------------------------------------------------------------------
#define ROWS_TOTAL 50176        // 256*14*14
#define KDIM       384
#define NDIM       1536
#define M_TILE     128
#define N_TILE     96
#define K_CHUNK    32
#define NUM_KC     (KDIM / K_CHUNK)   // 12
#define STAGES     4
#define LN_EPS     1e-6f

// fp16 scratch (no cudaMalloc allowed -> __device__ globals)
__device__ __half g_xh[(size_t)ROWS_TOTAL * KDIM];   // LN-applied X, fp16
__device__ __half g_wh[(size_t)NDIM * KDIM];         // W, fp16

// ---------------------------------------------------------------------------
// Inline PTX (baseline features only: ldmatrix / mma.sync / cp.async)
// ---------------------------------------------------------------------------
__device__ __forceinline__ uint32_t smem_u32(const void* p) {
    uint32_t a;
    asm("{ .reg .u64 t; cvta.to.shared.u64 t, %1; cvt.u32.u64 %0, t; }"
        : "=r"(a) : "l"(p));
    return a;
}

#define CP_ASYNC16(saddr, gptr) \
    asm volatile("cp.async.cg.shared.global [%0], [%1], 16;" \
                 :: "r"(saddr), "l"(gptr))

#define CP_COMMIT() asm volatile("cp.async.commit_group;")
#define CP_WAIT(n)  asm volatile("cp.async.wait_group %0;" :: "n"(n))

#define LDSM_X4(r, addr) \
    asm volatile("ldmatrix.sync.aligned.m8n8.x4.shared.b16 {%0,%1,%2,%3}, [%4];" \
                 : "=r"((r)[0]), "=r"((r)[1]), "=r"((r)[2]), "=r"((r)[3]) \
                 : "r"(addr))

#define MMA16816(c, a, b0v, b1v) \
    asm volatile("mma.sync.aligned.m16n8k16.row.col.f32.f16.f16.f32 " \
                 "{%0,%1,%2,%3}, {%4,%5,%6,%7}, {%8,%9}, {%0,%1,%2,%3};" \
                 : "+f"((c)[0]), "+f"((c)[1]), "+f"((c)[2]), "+f"((c)[3]) \
                 : "r"((a)[0]), "r"((a)[1]), "r"((a)[2]), "r"((a)[3]), \
                   "r"(b0v), "r"(b1v))

// ---------------------------------------------------------------------------
// SMEM: per stage { A [128][40] | B [96][40] }, 80B padded rows (conflict-free)
// ---------------------------------------------------------------------------
#define ROW_B      80
#define OFF_A      0
#define OFF_B      (M_TILE * ROW_B)               // 10240
#define STAGE_B    ((M_TILE + N_TILE) * ROW_B)    // 17920
#define SMEM_TOTAL (STAGES * STAGE_B)             // 71680 -> 3 CTAs/SM (215KB)

// Fast GELU: v * sigmoid(1.59577(v + 0.044715 v^3)) — branch-free, 2 MUFU.
__device__ __forceinline__ float gelu_fast(float v) {
    float t = v * v;
    float z = 1.5957691216f * v * fmaf(0.044715f, t, 1.0f);
    float e = __expf(-z);
    return __fdividef(v, 1.0f + e);
}

// ---------------------------------------------------------------------------
// Kernel 1: fused prepass. Blocks [0, 6272): LayerNorm -> fp16 X.
//           Blocks [6272, 6848): W fp32 -> fp16 convert.
// ---------------------------------------------------------------------------
#define LN_BLOCKS  (ROWS_TOTAL / 8)            // 6272
#define WC_BLOCKS  ((NDIM * KDIM) / 1024)      // 576

__global__ __launch_bounds__(256) void prepass_kernel(
    const float* __restrict__ x,
    const float* __restrict__ gamma,
    const float* __restrict__ beta,
    const float* __restrict__ W)
{
    if (blockIdx.x >= LN_BLOCKS) {
        int idx = ((blockIdx.x - LN_BLOCKS) * 256 + threadIdx.x) * 4;
        float4 wv = *reinterpret_cast<const float4*>(W + idx);
        __half2* p = reinterpret_cast<__half2*>(g_wh + idx);
        p[0] = __half2(__float2half_rn(wv.x), __float2half_rn(wv.y));
        p[1] = __half2(__float2half_rn(wv.z), __float2half_rn(wv.w));
        return;
    }

    int row  = blockIdx.x * 8 + (threadIdx.x >> 5);
    int lane = threadIdx.x & 31;
    const float4* xr = reinterpret_cast<const float4*>(x + (size_t)row * KDIM);

    float4 v[3];
    float s = 0.f, ss = 0.f;
#pragma unroll
    for (int i = 0; i < 3; i++) {
        v[i] = xr[lane + i * 32];
        s  += v[i].x + v[i].y + v[i].z + v[i].w;
        ss += v[i].x * v[i].x + v[i].y * v[i].y + v[i].z * v[i].z + v[i].w * v[i].w;
    }
#pragma unroll
    for (int o = 16; o > 0; o >>= 1) {
        s  += __shfl_xor_sync(0xffffffffu, s, o);
        ss += __shfl_xor_sync(0xffffffffu, ss, o);
    }
    float mu  = s * (1.0f / KDIM);
    float var = ss * (1.0f / KDIM) - mu * mu;
    float rs  = rsqrtf(var + LN_EPS);

#pragma unroll
    for (int i = 0; i < 3; i++) {
        int col = (lane + i * 32) * 4;
        float4 gv = *reinterpret_cast<const float4*>(gamma + col);
        float4 bv = *reinterpret_cast<const float4*>(beta + col);
        float n0 = fmaf(v[i].x - mu, rs * gv.x, bv.x);
        float n1 = fmaf(v[i].y - mu, rs * gv.y, bv.y);
        float n2 = fmaf(v[i].z - mu, rs * gv.z, bv.z);
        float n3 = fmaf(v[i].w - mu, rs * gv.w, bv.w);

        __half2* p = reinterpret_cast<__half2*>(g_xh + (size_t)row * KDIM + col);
        p[0] = __half2(__float2half_rn(n0), __float2half_rn(n1));
        p[1] = __half2(__float2half_rn(n2), __float2half_rn(n3));
    }
}

// ---------------------------------------------------------------------------
// Kernel 2: fp16 GEMM + bias + fast GELU
// CTA tile 128x96; 8 warps (4M x 2N), warp tile 32x48.
// 4-stage cp.async pipeline, 3 CTAs/SM.
// ---------------------------------------------------------------------------
__global__ __launch_bounds__(256, 3) void gemm_kernel(
    const float* __restrict__ bias,
    float* __restrict__ out)
{
    extern __shared__ char smem[];
    const uint32_t smem_base = smem_u32(smem);

    const int tid    = threadIdx.x;
    const int wid    = tid >> 5;
    const int lane   = tid & 31;
    const int warp_m = wid & 3;          // 0..3 (32-row quarters)
    const int warp_n = wid >> 2;         // 0..1 (48-col halves)
    const int lrow   = lane & 15;
    const int lsel   = lane >> 4;

    const int n0 = blockIdx.x * N_TILE;  // n fastest -> X-tile L2 reuse
    const int m0 = blockIdx.y * M_TILE;

    // --- per-thread load pointers ---
    // A: 512 16B-chunks (rows 0..127), 2 per thread.
    // B: 384 16B-chunks (rows 0..95), 1 per thread + 1 more for tid<128.
    const int ldr = tid >> 2;            // 0..63
    const int ldc = tid & 3;             // 16B chunk in row
    const __half* pa = g_xh + (size_t)(m0 + ldr) * KDIM + ldc * 8;
    const __half* pb = g_wh + (size_t)(n0 + ldr) * KDIM + ldc * 8;
    const uint32_t so = (uint32_t)(ldr * ROW_B + ldc * 16);
    const bool b2 = (tid < 128);         // loads B rows 64..95

#define LOAD_STAGE(sb, k0)                                               \
    do {                                                                 \
        CP_ASYNC16((sb) + OFF_A + so,            pa + (k0));             \
        CP_ASYNC16((sb) + OFF_A + so + 64*ROW_B, pa + 64*KDIM + (k0));   \
        CP_ASYNC16((sb) + OFF_B + so,            pb + (k0));             \
        if (b2)                                                          \
            CP_ASYNC16((sb) + OFF_B + so + 64*ROW_B, pb + 64*KDIM + (k0)); \
    } while (0)

    // --- hoisted ldmatrix base offsets ---
    uint32_t a_base[2], b_base[3];
#pragma unroll
    for (int mf = 0; mf < 2; mf++)
        a_base[mf] = (uint32_t)(OFF_A + (warp_m * 32 + mf * 16 + lrow) * ROW_B + lsel * 16);
#pragma unroll
    for (int nf2 = 0; nf2 < 3; nf2++)
        b_base[nf2] = (uint32_t)(OFF_B + (warp_n * 48 + nf2 * 16 + lrow) * ROW_B + lsel * 16);

    // prologue: prefetch STAGES-1 stages
#pragma unroll
    for (int s = 0; s < STAGES - 1; s++) {
        LOAD_STAGE(smem_base + s * STAGE_B, s * K_CHUNK);
        CP_COMMIT();
    }

    float acc[2][6][4];
#pragma unroll
    for (int a = 0; a < 2; a++)
#pragma unroll
        for (int b = 0; b < 6; b++)
#pragma unroll
            for (int c = 0; c < 4; c++) acc[a][b][c] = 0.f;

#pragma unroll
    for (int kc = 0; kc < NUM_KC; kc++) {
        CP_WAIT(STAGES - 2);
        __syncthreads();

        if (kc + STAGES - 1 < NUM_KC) {
            LOAD_STAGE(smem_base + ((kc + STAGES - 1) % STAGES) * STAGE_B,
                       (kc + STAGES - 1) * K_CHUNK);
        }
        CP_COMMIT();

        const uint32_t st = smem_base + (kc % STAGES) * STAGE_B;

#pragma unroll
        for (int ks = 0; ks < 2; ks++) {
            uint32_t af[2][4], bf[3][4];
#pragma unroll
            for (int nf2 = 0; nf2 < 3; nf2++)
                LDSM_X4(bf[nf2], st + b_base[nf2] + ks * 32);
#pragma unroll
            for (int mf = 0; mf < 2; mf++)
                LDSM_X4(af[mf], st + a_base[mf] + ks * 32);
#pragma unroll
            for (int mf = 0; mf < 2; mf++) {
#pragma unroll
                for (int nf = 0; nf < 6; nf++) {
                    const int g = nf >> 1, sel = nf & 1;
                    MMA16816(acc[mf][nf], af[mf], bf[g][sel], bf[g][sel + 2]);
                }
            }
        }
    }

    // epilogue: bias + fast GELU, direct float2 stores (sectors fully covered)
    const int tg = lane & 3, gp = lane >> 2;
#pragma unroll
    for (int mf = 0; mf < 2; mf++) {
#pragma unroll
        for (int nf = 0; nf < 6; nf++) {
            int row = m0 + warp_m * 32 + mf * 16 + gp;
            int col = n0 + warp_n * 48 + nf * 8 + tg * 2;
            float2 bv = *reinterpret_cast<const float2*>(bias + col);
            float2 o0, o1;
            o0.x = gelu_fast(acc[mf][nf][0] + bv.x);
            o0.y = gelu_fast(acc[mf][nf][1] + bv.y);
            o1.x = gelu_fast(acc[mf][nf][2] + bv.x);
            o1.y = gelu_fast(acc[mf][nf][3] + bv.y);
            *reinterpret_cast<float2*>(out + (size_t)row * NDIM + col) = o0;
            *reinterpret_cast<float2*>(out + (size_t)(row + 8) * NDIM + col) = o1;
        }
    }
#undef LOAD_STAGE
}

// ---------------------------------------------------------------------------
// Launch
// ---------------------------------------------------------------------------
extern "C" void kernel_launch(void* const* d_in, const int* in_sizes, int n_in,
                              void* d_out, int out_size) {
    const float* x     = (const float*)d_in[0];
    const float* gamma = (const float*)d_in[1];
    const float* beta  = (const float*)d_in[2];
    const float* W     = (const float*)d_in[3];
    const float* b     = (const float*)d_in[4];
    float* out = (float*)d_out;

    prepass_kernel<<<LN_BLOCKS + WC_BLOCKS, 256>>>(x, gamma, beta, W);

    cudaFuncSetAttribute(gemm_kernel,
                         cudaFuncAttributeMaxDynamicSharedMemorySize, SMEM_TOTAL);
    dim3 grid(NDIM / N_TILE, ROWS_TOTAL / M_TILE);   // (16, 392)
    gemm_kernel<<<grid, 256, SMEM_TOTAL>>>(b, out);
}